// round 1
// baseline (speedup 1.0000x reference)
#include <cuda_runtime.h>
#include <math.h>

// Problem constants
#define NB    64      // batch
#define CCH   256     // channels
#define HH    64
#define WW    44
#define GG    16      // stripes
#define SHH   4       // stripe height
#define PPX   176     // SHH*WW pixels per stripe
#define KL    4       // latents per stripe
#define TOPKK 22      // int(176*0.125)
#define TEMP_INV 8.0f // 1/0.125
#define GATE_THR 0.05f

#define XSTR 177      // odd stride -> conflict-free for both access patterns
#define YSTR 180

// Output layout (flat concatenation of the 4 reference outputs)
#define TOK_ELEMS   (NB*CCH*GG*KL)          // 1,048,576
#define PRES_ELEMS  (NB*GG*KL)              // 4,096
#define MAP_ELEMS   (NB*HH*WW*GG*KL)        // 11,534,336

struct SM {
    float xs[CCH*XSTR];     // x stripe, layout [c][p], stride 177
    float lbn4[CCH*4];      // normalized latent basis, packed [c][k] for LDS.128
    float yd[4*YSTR];       // raw projections y[k][p]
    float dotp[PPX*4];      // pooled projections, packed [p][k]
    float sup[PPX*4];       // support (routing result), packed [p][k]
    float pw[PPX*4];        // pool weights, packed [p][k]
    float fe[PPX];
    float npart[8*PPX];     // per-warp norm partials
    float nrm[PPX];
    float red[32];
    float scal[16];
};

__device__ __forceinline__ float wsum(float v) {
#pragma unroll
    for (int o = 16; o; o >>= 1) v += __shfl_xor_sync(0xffffffffu, v, o);
    return v;
}
__device__ __forceinline__ float wmaxr(float v) {
#pragma unroll
    for (int o = 16; o; o >>= 1) v = fmaxf(v, __shfl_xor_sync(0xffffffffu, v, o));
    return v;
}

__global__ void __launch_bounds__(256, 1)
fused_stripe_kernel(const float* __restrict__ x, const float* __restrict__ lb,
                    float* __restrict__ out_tok, float* __restrict__ out_pres,
                    float* __restrict__ out_smap, float* __restrict__ out_pmap)
{
    extern __shared__ float sraw[];
    SM& s = *reinterpret_cast<SM*>(sraw);
    const int tid = threadIdx.x, lane = tid & 31, wid = tid >> 5;
    const int blk = blockIdx.x;
    const int n = blk >> 4, g = blk & 15;

    // ---------- Phase 1: load + L2-normalize latent basis for this stripe ----------
    {
        const float* lbg = lb + (size_t)g * (KL * CCH);
        const int c = tid;
        float v0 = lbg[c], v1 = lbg[CCH + c], v2 = lbg[2 * CCH + c], v3 = lbg[3 * CCH + c];
        float s0 = wsum(v0 * v0), s1 = wsum(v1 * v1), s2 = wsum(v2 * v2), s3 = wsum(v3 * v3);
        if (lane == 0) { s.red[wid] = s0; s.red[8 + wid] = s1; s.red[16 + wid] = s2; s.red[24 + wid] = s3; }
        __syncthreads();
        if (tid < 4) {
            float ss = 0.f;
#pragma unroll
            for (int j = 0; j < 8; ++j) ss += s.red[tid * 8 + j];
            s.scal[tid] = 1.0f / fmaxf(sqrtf(ss), 1e-12f);
        }
        __syncthreads();
        float4 o4 = make_float4(v0 * s.scal[0], v1 * s.scal[1], v2 * s.scal[2], v3 * s.scal[3]);
        *reinterpret_cast<float4*>(&s.lbn4[c * 4]) = o4;
    }

    // ---------- Phase 2: load x stripe -> smem, transposed to [c][p] ----------
    {
        const float* xb = x + (size_t)n * (CCH * HH * WW) + (size_t)g * (SHH * WW);
        const int rot0 = lane + (lane >> 3);     // bank-conflict-free scalar scatter
#pragma unroll 4
        for (int it = 0; it < 44; ++it) {
            int idx = tid + 256 * it;            // 0..11263 float4 tiles
            int c = idx / 44, q = idx - 44 * c;
            float4 v = *reinterpret_cast<const float4*>(xb + (size_t)c * (HH * WW) + q * 4);
            float* dst = &s.xs[c * XSTR + q * 4];
            float vv[4] = { v.x, v.y, v.z, v.w };
#pragma unroll
            for (int st = 0; st < 4; ++st) {
                int m = (rot0 + st) & 3;
                dst[m] = vv[m];
            }
        }
    }
    __syncthreads();

    // ---------- Phase 3: projections y[k][p] = sum_c x[c][p]*lbn[k][c], plus fe[p] ----------
    if (tid < PPX) {
        const int p = tid;
        const float* xp = &s.xs[p];
        float d0 = 0, d1 = 0, d2 = 0, d3 = 0, feacc = 0;
#pragma unroll 4
        for (int c = 0; c < CCH; ++c) {
            float xv = xp[c * XSTR];
            float4 l4 = *reinterpret_cast<const float4*>(&s.lbn4[c * 4]);
            feacc = fmaf(xv, xv, feacc);
            d0 = fmaf(xv, l4.x, d0); d1 = fmaf(xv, l4.y, d1);
            d2 = fmaf(xv, l4.z, d2); d3 = fmaf(xv, l4.w, d3);
        }
        s.yd[0 * YSTR + p] = d0; s.yd[1 * YSTR + p] = d1;
        s.yd[2 * YSTR + p] = d2; s.yd[3 * YSTR + p] = d3;
        s.fe[p] = feacc * (1.0f / CCH);
    }
    __syncthreads();

    // ---------- Phase 4: fe max + active count ----------
    if (wid == 0) {
        float m = 0.f;
        for (int j = lane; j < PPX; j += 32) m = fmaxf(m, s.fe[j]);
        m = wmaxr(m);
        if (lane == 0) s.scal[4] = 1.0f / fmaxf(m, 1e-6f);
    }
    __syncthreads();
    const float invmax = s.scal[4];
    int pred = (tid < PPX) && (s.fe[tid] * invmax > GATE_THR);
    int cnt = __syncthreads_count(pred);   // also a barrier

    // ---------- Phase 5: pool the 4 projection maps (3x3 avg, zero pad, /9) ----------
    for (int idx = tid; idx < PPX * 4; idx += 256) {
        int p = idx >> 2, k = idx & 3;
        int r = p / 44, w0 = p - r * 44;
        const float* yk = &s.yd[k * YSTR];
        float acc = 0.f;
#pragma unroll
        for (int dr = -1; dr <= 1; ++dr) {
            int rr = r + dr;
            bool rok = (rr >= 0) && (rr < SHH);
#pragma unroll
            for (int dw = -1; dw <= 1; ++dw) {
                int w2 = w0 + dw;
                if (rok && w2 >= 0 && w2 < WW) acc += yk[rr * 44 + w2];
            }
        }
        s.dotp[idx] = acc * (1.0f / 9.0f);
    }

    // ---------- Phase 6: support-vector norm via rolling separable 3x3 ----------
    // warp `wid` owns channels c = wid*32+lane; walk columns; shfl-reduce across lanes(=channels)
    {
        const float* xc = &s.xs[tid * XSTR];
        float a0 = 0, a1 = 0, a2 = 0, a3 = 0;                       // column w-1
        float b0 = xc[0], b1 = xc[44], b2 = xc[88], b3 = xc[132];   // column w
        float* np = &s.npart[wid * PPX];
        for (int w2 = 0; w2 < 44; ++w2) {
            float c0, c1, c2, c3;
            if (w2 < 43) { c0 = xc[w2 + 1]; c1 = xc[45 + w2]; c2 = xc[89 + w2]; c3 = xc[133 + w2]; }
            else         { c0 = c1 = c2 = c3 = 0.f; }
            float h0 = a0 + b0 + c0, h1 = a1 + b1 + c1, h2 = a2 + b2 + c2, h3 = a3 + b3 + c3;
            float v0 = h0 + h1;
            float v1 = v0 + h2;
            float v2 = h1 + h2 + h3;
            float v3 = h2 + h3;
            float q0 = wsum(v0 * v0), q1 = wsum(v1 * v1), q2 = wsum(v2 * v2), q3 = wsum(v3 * v3);
            if (lane == 0) { np[w2] = q0; np[44 + w2] = q1; np[88 + w2] = q2; np[132 + w2] = q3; }
            a0 = b0; a1 = b1; a2 = b2; a3 = b3;
            b0 = c0; b1 = c1; b2 = c2; b3 = c3;
        }
    }
    __syncthreads();
    if (tid < PPX) {
        float acc = 0.f;
#pragma unroll
        for (int j = 0; j < 8; ++j) acc += s.npart[j * PPX + tid];
        s.nrm[tid] = acc * (1.0f / 81.0f);   // pooled values carry 1/9 each -> 1/81 on squares
    }
    __syncthreads();

    // ---------- Phase 7: routing softmax + active gating -> support ----------
    if (tid < PPX) {
        const int p = tid;
        float4 d = *reinterpret_cast<float4*>(&s.dotp[p * 4]);
        float rn = 1.0f / fmaxf(sqrtf(s.nrm[p]), 1e-12f);
        float sc = rn * TEMP_INV;
        float l0 = d.x * sc, l1 = d.y * sc, l2 = d.z * sc, l3 = d.w * sc;
        float m = fmaxf(fmaxf(l0, l1), fmaxf(l2, l3));
        float e0 = __expf(l0 - m), e1 = __expf(l1 - m), e2 = __expf(l2 - m), e3 = __expf(l3 - m);
        float inv = 1.0f / (e0 + e1 + e2 + e3);
        float fes = s.fe[p] * invmax;
        float act = (cnt > 0) ? (fes > GATE_THR ? 1.f : 0.f) : (fes > 0.f ? 1.f : 0.f);
        float w_ = inv * act;
        *reinterpret_cast<float4*>(&s.sup[p * 4]) = make_float4(e0 * w_, e1 * w_, e2 * w_, e3 * w_);
    }
    __syncthreads();

    // ---------- Phase 8: pool sums (warp 0) + top-22 presence (warps 4-7) ----------
    if (wid == 0) {
        float s0 = 0, s1 = 0, s2 = 0, s3 = 0;
        for (int p = lane; p < PPX; p += 32) {
            float4 v = *reinterpret_cast<float4*>(&s.sup[p * 4]);
            s0 += v.x; s1 += v.y; s2 += v.z; s3 += v.w;
        }
        s0 = wsum(s0); s1 = wsum(s1); s2 = wsum(s2); s3 = wsum(s3);
        if (lane == 0) {
            s.scal[8]  = 1.0f / fmaxf(s0, 1e-6f);
            s.scal[9]  = 1.0f / fmaxf(s1, 1e-6f);
            s.scal[10] = 1.0f / fmaxf(s2, 1e-6f);
            s.scal[11] = 1.0f / fmaxf(s3, 1e-6f);
        }
    }
    if (wid >= 4) {
        const int k = wid - 4;
        float v[6];
#pragma unroll
        for (int j = 0; j < 6; ++j) {
            int p = lane + 32 * j;
            v[j] = (p < PPX) ? s.sup[p * 4 + k] : -1.0f;
        }
        float sum = 0.f;
        for (int it = 0; it < TOPKK; ++it) {
            float lm = v[0]; int li = 0;
#pragma unroll
            for (int j = 1; j < 6; ++j) { if (v[j] > lm) { lm = v[j]; li = j; } }
            float wm = wmaxr(lm);
            unsigned msk = __ballot_sync(0xffffffffu, lm == wm);
            int src = __ffs(msk) - 1;
            if (lane == src) v[li] = -1.0f;     // remove exactly one instance
            sum += wm;
        }
        if (lane == 0) out_pres[n * 64 + g * 4 + k] = sum * (1.0f / TOPKK);
    }
    __syncthreads();

    // ---------- Phase 9: pool weights ----------
    if (tid < PPX) {
        float4 v = *reinterpret_cast<float4*>(&s.sup[tid * 4]);
        *reinterpret_cast<float4*>(&s.pw[tid * 4]) =
            make_float4(v.x * s.scal[8], v.y * s.scal[9], v.z * s.scal[10], v.w * s.scal[11]);
    }
    __syncthreads();

    // ---------- Phase 10: tokens[k][c] = sum_p pw[p][k] * x[c][p] ----------
    {
        const int c = tid;
        const float* xc = &s.xs[c * XSTR];
        float t0 = 0, t1 = 0, t2 = 0, t3 = 0;
#pragma unroll 4
        for (int p = 0; p < PPX; ++p) {
            float xv = xc[p];
            float4 w4 = *reinterpret_cast<const float4*>(&s.pw[p * 4]);
            t0 = fmaf(xv, w4.x, t0); t1 = fmaf(xv, w4.y, t1);
            t2 = fmaf(xv, w4.z, t2); t3 = fmaf(xv, w4.w, t3);
        }
        *reinterpret_cast<float4*>(out_tok + ((size_t)(n * CCH + c) * 64 + g * 4)) =
            make_float4(t0, t1, t2, t3);
    }

    // ---------- Phase 11: scatter support / pool-weight maps (dense rows, zeros elsewhere) ----------
    {
        float* smb = out_smap + (size_t)n * (HH * WW * 64) + (size_t)g * (PPX * 64);
        float* pmb = out_pmap + (size_t)n * (HH * WW * 64) + (size_t)g * (PPX * 64);
        const float4 z4 = make_float4(0.f, 0.f, 0.f, 0.f);
#pragma unroll
        for (int i = 0; i < 11; ++i) {
            int idx = tid + 256 * i;      // 0..2815 float4 slots per map
            int p = idx >> 4, qd = idx & 15;
            float4 sv = z4, pv = z4;
            if (qd == g) {
                sv = *reinterpret_cast<float4*>(&s.sup[p * 4]);
                pv = *reinterpret_cast<float4*>(&s.pw[p * 4]);
            }
            *reinterpret_cast<float4*>(smb + (size_t)idx * 4) = sv;
            *reinterpret_cast<float4*>(pmb + (size_t)idx * 4) = pv;
        }
    }
}

// Normalize presence per batch element (sum over 64 entries)
__global__ void presence_norm_kernel(float* __restrict__ pres)
{
    const int n = blockIdx.x, lane = threadIdx.x;
    float a = pres[n * 64 + lane];
    float b = pres[n * 64 + 32 + lane];
    float t = a + b;
#pragma unroll
    for (int o = 16; o; o >>= 1) t += __shfl_xor_sync(0xffffffffu, t, o);
    float inv = 1.0f / fmaxf(t, 1e-6f);
    pres[n * 64 + lane] = a * inv;
    pres[n * 64 + 32 + lane] = b * inv;
}

extern "C" void kernel_launch(void* const* d_in, const int* in_sizes, int n_in,
                              void* d_out, int out_size)
{
    const float* x  = (const float*)d_in[0];
    const float* lb = (const float*)d_in[1];
    float* out = (float*)d_out;

    float* tok  = out;
    float* pres = out + TOK_ELEMS;
    float* smap = out + TOK_ELEMS + PRES_ELEMS;
    float* pmap = out + TOK_ELEMS + PRES_ELEMS + MAP_ELEMS;

    cudaFuncSetAttribute(fused_stripe_kernel,
                         cudaFuncAttributeMaxDynamicSharedMemorySize, (int)sizeof(SM));
    fused_stripe_kernel<<<NB * GG, 256, sizeof(SM)>>>(x, lb, tok, pres, smap, pmap);
    presence_norm_kernel<<<NB, 32>>>(pres);
}

// round 2
// speedup vs baseline: 1.1468x; 1.1468x over previous
#include <cuda_runtime.h>
#include <math.h>

// Problem constants
#define NB    64      // batch
#define CCH   256     // channels
#define HH    64
#define WW    44
#define GG    16      // stripes
#define SHH   4       // stripe height
#define PPX   176     // SHH*WW pixels per stripe
#define KL    4       // latents per stripe
#define TOPKK 22      // int(176*0.125)
#define TEMP_INV 8.0f // 1/0.125
#define GATE_THR 0.05f
#define THREADS 512

#define XSTR 177      // odd stride -> conflict-free for both access patterns
#define YSTR 180

// Output layout (flat concatenation of the 4 reference outputs)
#define TOK_ELEMS   (NB*CCH*GG*KL)          // 1,048,576
#define PRES_ELEMS  (NB*GG*KL)              // 4,096
#define MAP_ELEMS   (NB*HH*WW*GG*KL)        // 11,534,336

struct SM {
    float xs[CCH*XSTR];     // x stripe, layout [c][p], stride 177
    float lbn4[CCH*4];      // normalized latent basis, packed [c][k] for LDS.128
    float yd[4*YSTR];       // raw projections y[k][p]
    float dotp[PPX*4];      // pooled projections, packed [p][k]
    float sup[PPX*4];       // support (routing result), packed [p][k]
    float pw[PPX*4];        // pool weights, packed [p][k]
    float fe[PPX];
    float npart[8*PPX];     // scratch: proj partials / norm partials / token partials
    float nrm[PPX];
    float red[32];
    float scal[16];
};

__device__ __forceinline__ float wsum(float v) {
#pragma unroll
    for (int o = 16; o; o >>= 1) v += __shfl_xor_sync(0xffffffffu, v, o);
    return v;
}
__device__ __forceinline__ float wmaxr(float v) {
#pragma unroll
    for (int o = 16; o; o >>= 1) v = fmaxf(v, __shfl_xor_sync(0xffffffffu, v, o));
    return v;
}

__global__ void __launch_bounds__(THREADS, 1)
fused_stripe_kernel(const float* __restrict__ x, const float* __restrict__ lb,
                    float* __restrict__ out_tok, float* __restrict__ out_pres,
                    float* __restrict__ out_smap, float* __restrict__ out_pmap)
{
    extern __shared__ float sraw[];
    SM& s = *reinterpret_cast<SM*>(sraw);
    const int tid = threadIdx.x, lane = tid & 31, wid = tid >> 5;
    const int blk = blockIdx.x;
    const int n = blk >> 4, g = blk & 15;

    // ---------- Phase 1: load + L2-normalize latent basis ----------
    float v0 = 0, v1 = 0, v2 = 0, v3 = 0;
    if (tid < 256) {
        const float* lbg = lb + (size_t)g * (KL * CCH);
        v0 = lbg[tid]; v1 = lbg[CCH + tid]; v2 = lbg[2 * CCH + tid]; v3 = lbg[3 * CCH + tid];
        float s0 = wsum(v0 * v0), s1 = wsum(v1 * v1), s2 = wsum(v2 * v2), s3 = wsum(v3 * v3);
        if (lane == 0) { s.red[wid] = s0; s.red[8 + wid] = s1; s.red[16 + wid] = s2; s.red[24 + wid] = s3; }
    }
    __syncthreads();
    if (tid < 4) {
        float ss = 0.f;
#pragma unroll
        for (int j = 0; j < 8; ++j) ss += s.red[tid * 8 + j];
        s.scal[tid] = 1.0f / fmaxf(sqrtf(ss), 1e-12f);
    }
    __syncthreads();
    if (tid < 256) {
        float4 o4 = make_float4(v0 * s.scal[0], v1 * s.scal[1], v2 * s.scal[2], v3 * s.scal[3]);
        *reinterpret_cast<float4*>(&s.lbn4[tid * 4]) = o4;
    }

    // ---------- Phase 2: load x stripe -> smem, transposed to [c][p] ----------
    {
        const float* xb = x + (size_t)n * (CCH * HH * WW) + (size_t)g * (SHH * WW);
        const int rot0 = lane + (lane >> 3);     // bank-conflict-free scalar scatter
#pragma unroll 2
        for (int it = 0; it < 22; ++it) {
            int idx = tid + THREADS * it;        // 0..11263 float4 tiles
            int c = idx / 44, q = idx - 44 * c;
            float4 v = *reinterpret_cast<const float4*>(xb + (size_t)c * (HH * WW) + q * 4);
            float* dst = &s.xs[c * XSTR + q * 4];
            float vv[4] = { v.x, v.y, v.z, v.w };
#pragma unroll
            for (int st = 0; st < 4; ++st) {
                int m = (rot0 + st) & 3;
                dst[m] = vv[m];
            }
        }
    }
    __syncthreads();

    // ---------- Phase 3: projections split over channel halves ----------
    float d0 = 0, d1 = 0, d2 = 0, d3 = 0, feacc = 0;
    if (tid < 352) {
        const int half = (tid >= PPX);
        const int p = tid - (half ? PPX : 0);
        const int c0 = half * 128;
        const float* xp = &s.xs[p];
#pragma unroll 4
        for (int c = c0; c < c0 + 128; ++c) {
            float xv = xp[c * XSTR];
            float4 l4 = *reinterpret_cast<const float4*>(&s.lbn4[c * 4]);
            feacc = fmaf(xv, xv, feacc);
            d0 = fmaf(xv, l4.x, d0); d1 = fmaf(xv, l4.y, d1);
            d2 = fmaf(xv, l4.z, d2); d3 = fmaf(xv, l4.w, d3);
        }
        if (half) {
            s.npart[0 * PPX + p] = d0; s.npart[1 * PPX + p] = d1;
            s.npart[2 * PPX + p] = d2; s.npart[3 * PPX + p] = d3;
            s.npart[4 * PPX + p] = feacc;
        }
    }
    __syncthreads();
    if (tid < PPX) {
        d0 += s.npart[tid]; d1 += s.npart[PPX + tid];
        d2 += s.npart[2 * PPX + tid]; d3 += s.npart[3 * PPX + tid];
        feacc += s.npart[4 * PPX + tid];
        s.yd[0 * YSTR + tid] = d0; s.yd[1 * YSTR + tid] = d1;
        s.yd[2 * YSTR + tid] = d2; s.yd[3 * YSTR + tid] = d3;
        s.fe[tid] = feacc * (1.0f / CCH);
    }
    __syncthreads();

    // ---------- Phase 4: fe max + active count ----------
    if (wid == 0) {
        float m = 0.f;
        for (int j = lane; j < PPX; j += 32) m = fmaxf(m, s.fe[j]);
        m = wmaxr(m);
        if (lane == 0) s.scal[4] = 1.0f / fmaxf(m, 1e-6f);
    }
    __syncthreads();
    const float invmax = s.scal[4];
    int pred = (tid < PPX) && (s.fe[tid] * invmax > GATE_THR);
    int cnt = __syncthreads_count(pred);   // also a barrier

    // ---------- Phase 5: pool the 4 projection maps (3x3 avg, zero pad, /9) ----------
    for (int idx = tid; idx < PPX * 4; idx += THREADS) {
        int p = idx >> 2, k = idx & 3;
        int r = p / 44, w0 = p - r * 44;
        const float* yk = &s.yd[k * YSTR];
        float acc = 0.f;
#pragma unroll
        for (int dr = -1; dr <= 1; ++dr) {
            int rr = r + dr;
            bool rok = (rr >= 0) && (rr < SHH);
#pragma unroll
            for (int dw = -1; dw <= 1; ++dw) {
                int w2 = w0 + dw;
                if (rok && w2 >= 0 && w2 < WW) acc += yk[rr * 44 + w2];
            }
        }
        s.dotp[idx] = acc * (1.0f / 9.0f);
    }

    // ---------- Phase 6: support norm via rolling separable 3x3, 16 warps ----------
    // warp = (channel-group 0..7) x (column-half 0..1); lanes = 32 channels
    {
        const int chg = wid & 7, colh = wid >> 3;
        const int c = chg * 32 + lane;
        const int w0 = colh * 22;
        const float* xc = &s.xs[c * XSTR];
        float a0, a1, a2, a3, b0, b1, b2, b3;
        if (w0 > 0) { a0 = xc[w0 - 1]; a1 = xc[44 + w0 - 1]; a2 = xc[88 + w0 - 1]; a3 = xc[132 + w0 - 1]; }
        else        { a0 = a1 = a2 = a3 = 0.f; }
        b0 = xc[w0]; b1 = xc[44 + w0]; b2 = xc[88 + w0]; b3 = xc[132 + w0];
        float* np = &s.npart[chg * PPX];
        for (int w2 = w0; w2 < w0 + 22; ++w2) {
            float c0, c1, c2, c3;
            if (w2 < 43) { c0 = xc[w2 + 1]; c1 = xc[45 + w2]; c2 = xc[89 + w2]; c3 = xc[133 + w2]; }
            else         { c0 = c1 = c2 = c3 = 0.f; }
            float h0 = a0 + b0 + c0, h1 = a1 + b1 + c1, h2 = a2 + b2 + c2, h3 = a3 + b3 + c3;
            float u0 = h0 + h1;
            float u1 = u0 + h2;
            float u2 = h1 + h2 + h3;
            float u3 = h2 + h3;
            float q0 = wsum(u0 * u0), q1 = wsum(u1 * u1), q2 = wsum(u2 * u2), q3 = wsum(u3 * u3);
            if (lane == 0) { np[w2] = q0; np[44 + w2] = q1; np[88 + w2] = q2; np[132 + w2] = q3; }
            a0 = b0; a1 = b1; a2 = b2; a3 = b3;
            b0 = c0; b1 = c1; b2 = c2; b3 = c3;
        }
    }
    __syncthreads();
    if (tid < PPX) {
        float acc = 0.f;
#pragma unroll
        for (int j = 0; j < 8; ++j) acc += s.npart[j * PPX + tid];
        s.nrm[tid] = acc * (1.0f / 81.0f);
    }
    __syncthreads();

    // ---------- Phase 7: routing softmax + active gating -> support ----------
    if (tid < PPX) {
        const int p = tid;
        float4 d = *reinterpret_cast<float4*>(&s.dotp[p * 4]);
        float rn = 1.0f / fmaxf(sqrtf(s.nrm[p]), 1e-12f);
        float sc = rn * TEMP_INV;
        float l0 = d.x * sc, l1 = d.y * sc, l2 = d.z * sc, l3 = d.w * sc;
        float m = fmaxf(fmaxf(l0, l1), fmaxf(l2, l3));
        float e0 = __expf(l0 - m), e1 = __expf(l1 - m), e2 = __expf(l2 - m), e3 = __expf(l3 - m);
        float inv = 1.0f / (e0 + e1 + e2 + e3);
        float fes = s.fe[p] * invmax;
        float act = (cnt > 0) ? (fes > GATE_THR ? 1.f : 0.f) : (fes > 0.f ? 1.f : 0.f);
        float w_ = inv * act;
        *reinterpret_cast<float4*>(&s.sup[p * 4]) = make_float4(e0 * w_, e1 * w_, e2 * w_, e3 * w_);
    }
    __syncthreads();

    // ---------- Phase 8 (overlapped): pool sums | top-22 | smap scatter ----------
    if (wid == 0) {
        float s0 = 0, s1 = 0, s2 = 0, s3 = 0;
        for (int p = lane; p < PPX; p += 32) {
            float4 v = *reinterpret_cast<float4*>(&s.sup[p * 4]);
            s0 += v.x; s1 += v.y; s2 += v.z; s3 += v.w;
        }
        s0 = wsum(s0); s1 = wsum(s1); s2 = wsum(s2); s3 = wsum(s3);
        if (lane == 0) {
            s.scal[8]  = 1.0f / fmaxf(s0, 1e-6f);
            s.scal[9]  = 1.0f / fmaxf(s1, 1e-6f);
            s.scal[10] = 1.0f / fmaxf(s2, 1e-6f);
            s.scal[11] = 1.0f / fmaxf(s3, 1e-6f);
        }
    } else if (wid >= 4 && wid < 8) {
        const int k = wid - 4;
        float v[6];
#pragma unroll
        for (int j = 0; j < 6; ++j) {
            int p = lane + 32 * j;
            v[j] = (p < PPX) ? s.sup[p * 4 + k] : -1.0f;
        }
        float sum = 0.f;
        for (int it = 0; it < TOPKK; ++it) {
            float lm = v[0]; int li = 0;
#pragma unroll
            for (int j = 1; j < 6; ++j) { if (v[j] > lm) { lm = v[j]; li = j; } }
            float wm = wmaxr(lm);
            unsigned msk = __ballot_sync(0xffffffffu, lm == wm);
            int src = __ffs(msk) - 1;
            if (lane == src) v[li] = -1.0f;     // remove exactly one instance
            sum += wm;
        }
        if (lane == 0) out_pres[n * 64 + g * 4 + k] = sum * (1.0f / TOPKK);
    } else {
        // warps 1-3 and 8-15 (11 warps = 352 threads): scatter smap now
        int st = ((wid < 4) ? (wid - 1) : (wid - 5)) * 32 + lane;   // 0..351
        float* smb = out_smap + (size_t)n * (HH * WW * 64) + (size_t)g * (PPX * 64);
        const float4 z4 = make_float4(0.f, 0.f, 0.f, 0.f);
#pragma unroll
        for (int idx = st; idx < 2816; idx += 352) {
            int p = idx >> 4, qd = idx & 15;
            float4 sv = (qd == g) ? *reinterpret_cast<float4*>(&s.sup[p * 4]) : z4;
            *reinterpret_cast<float4*>(smb + (size_t)idx * 4) = sv;
        }
    }
    __syncthreads();

    // ---------- Phase 9: pool weights ----------
    if (tid < PPX) {
        float4 v = *reinterpret_cast<float4*>(&s.sup[tid * 4]);
        *reinterpret_cast<float4*>(&s.pw[tid * 4]) =
            make_float4(v.x * s.scal[8], v.y * s.scal[9], v.z * s.scal[10], v.w * s.scal[11]);
    }
    __syncthreads();

    // ---------- Phase 10: tokens split over p-halves ----------
    {
        const int c = tid & 255, half = tid >> 8;
        const float* xc = &s.xs[c * XSTR + half * 88];
        const float* pwp = &s.pw[half * 88 * 4];
        float t0 = 0, t1 = 0, t2 = 0, t3 = 0;
#pragma unroll 4
        for (int p = 0; p < 88; ++p) {
            float xv = xc[p];
            float4 w4 = *reinterpret_cast<const float4*>(&pwp[p * 4]);
            t0 = fmaf(xv, w4.x, t0); t1 = fmaf(xv, w4.y, t1);
            t2 = fmaf(xv, w4.z, t2); t3 = fmaf(xv, w4.w, t3);
        }
        if (half) {
            s.npart[c] = t0; s.npart[256 + c] = t1;
            s.npart[512 + c] = t2; s.npart[768 + c] = t3;
        }
        __syncthreads();
        if (!half) {
            t0 += s.npart[c]; t1 += s.npart[256 + c];
            t2 += s.npart[512 + c]; t3 += s.npart[768 + c];
            *reinterpret_cast<float4*>(out_tok + ((size_t)(n * CCH + c) * 64 + g * 4)) =
                make_float4(t0, t1, t2, t3);
        } else {
            // ---------- Phase 11: scatter pmap (256 threads) ----------
            float* pmb = out_pmap + (size_t)n * (HH * WW * 64) + (size_t)g * (PPX * 64);
            const float4 z4 = make_float4(0.f, 0.f, 0.f, 0.f);
            int t2i = tid - 256;
#pragma unroll
            for (int i = 0; i < 11; ++i) {
                int idx = t2i + 256 * i;      // 0..2815 float4 slots
                int p = idx >> 4, qd = idx & 15;
                float4 pv = (qd == g) ? *reinterpret_cast<float4*>(&s.pw[p * 4]) : z4;
                *reinterpret_cast<float4*>(pmb + (size_t)idx * 4) = pv;
            }
        }
    }
}

// Normalize presence per batch element (sum over 64 entries)
__global__ void presence_norm_kernel(float* __restrict__ pres)
{
    const int n = blockIdx.x, lane = threadIdx.x;
    float a = pres[n * 64 + lane];
    float b = pres[n * 64 + 32 + lane];
    float t = a + b;
#pragma unroll
    for (int o = 16; o; o >>= 1) t += __shfl_xor_sync(0xffffffffu, t, o);
    float inv = 1.0f / fmaxf(t, 1e-6f);
    pres[n * 64 + lane] = a * inv;
    pres[n * 64 + 32 + lane] = b * inv;
}

extern "C" void kernel_launch(void* const* d_in, const int* in_sizes, int n_in,
                              void* d_out, int out_size)
{
    const float* x  = (const float*)d_in[0];
    const float* lb = (const float*)d_in[1];
    float* out = (float*)d_out;

    float* tok  = out;
    float* pres = out + TOK_ELEMS;
    float* smap = out + TOK_ELEMS + PRES_ELEMS;
    float* pmap = out + TOK_ELEMS + PRES_ELEMS + MAP_ELEMS;

    cudaFuncSetAttribute(fused_stripe_kernel,
                         cudaFuncAttributeMaxDynamicSharedMemorySize, (int)sizeof(SM));
    fused_stripe_kernel<<<NB * GG, THREADS, sizeof(SM)>>>(x, lb, tok, pres, smap, pmap);
    presence_norm_kernel<<<NB, 32>>>(pres);
}